// round 3
// baseline (speedup 1.0000x reference)
#include <cuda_runtime.h>
#include <math.h>

#define TT 4096
#define DIM 1024
#define HEADS 16
#define HD 64
#define MLPD 4096

// ---------------- scratch (device globals; no allocation allowed) ----------------
__device__ float g_ada[6 * DIM];
__device__ float g_h[TT * DIM];
__device__ float g_qkv[TT * 3 * DIM];
__device__ float g_o[TT * DIM];
__device__ float g_x1[TT * DIM];
__device__ float g_h2[TT * DIM];
__device__ float g_m[TT * MLPD];

// ---------------- helpers ----------------
__device__ __forceinline__ float gelu_tanh(float x) {
    float x3 = x * x * x;
    return 0.5f * x * (1.0f + tanhf(0.7978845608028654f * (x + 0.044715f * x3)));
}

// ---------------- ada = c @ w_ada + b_ada  (1x1024 @ 1024x6144) ----------------
__global__ void ada_kernel(const float* __restrict__ c, const float* __restrict__ w,
                           const float* __restrict__ b) {
    int j = blockIdx.x * blockDim.x + threadIdx.x;  // < 6144
    float s = b[j];
    for (int k = 0; k < DIM; k++) s += c[k] * w[k * 6144 + j];
    g_ada[j] = s;
}

// ---------------- LN + adaLN modulation: out = ln(x)*(1+sc)+sh ----------------
__global__ void ln_mod_kernel(const float* __restrict__ x, const float* __restrict__ w,
                              const float* __restrict__ bb, const float* __restrict__ sc,
                              const float* __restrict__ sh, float* __restrict__ out) {
    int t = blockIdx.x;
    int tid = threadIdx.x;
    int lane = tid & 31, wid = tid >> 5;
    __shared__ float red[8];
    float4 v = reinterpret_cast<const float4*>(x + (size_t)t * DIM)[tid];

    float s = v.x + v.y + v.z + v.w;
#pragma unroll
    for (int o = 16; o > 0; o >>= 1) s += __shfl_xor_sync(0xffffffffu, s, o);
    if (lane == 0) red[wid] = s;
    __syncthreads();
    float mu = 0.f;
#pragma unroll
    for (int i = 0; i < 8; i++) mu += red[i];
    mu *= (1.0f / DIM);

    float d0 = v.x - mu, d1 = v.y - mu, d2 = v.z - mu, d3 = v.w - mu;
    float ss = d0 * d0 + d1 * d1 + d2 * d2 + d3 * d3;
    __syncthreads();
#pragma unroll
    for (int o = 16; o > 0; o >>= 1) ss += __shfl_xor_sync(0xffffffffu, ss, o);
    if (lane == 0) red[wid] = ss;
    __syncthreads();
    float var = 0.f;
#pragma unroll
    for (int i = 0; i < 8; i++) var += red[i];
    var *= (1.0f / DIM);
    float rs = rsqrtf(var + 1e-5f);

    int j = tid * 4;
    float o0 = (d0 * rs * w[j + 0] + bb[j + 0]) * (1.0f + sc[j + 0]) + sh[j + 0];
    float o1 = (d1 * rs * w[j + 1] + bb[j + 1]) * (1.0f + sc[j + 1]) + sh[j + 1];
    float o2 = (d2 * rs * w[j + 2] + bb[j + 2]) * (1.0f + sc[j + 2]) + sh[j + 2];
    float o3 = (d3 * rs * w[j + 3] + bb[j + 3]) * (1.0f + sc[j + 3]) + sh[j + 3];
    reinterpret_cast<float4*>(out + (size_t)t * DIM)[tid] = make_float4(o0, o1, o2, o3);
}

// ---------------- generic NN SGEMM, 128x128x8 tiles, 8x8 microtile -----------
// MODE 0: C = A@B
// MODE 1: C = gelu(A@B + bias)
// MODE 2: C = resid + gate[col]*(A@B + bias?)
template <int MODE>
__global__ void sgemm_kernel(const float* __restrict__ A, const float* __restrict__ B,
                             float* __restrict__ C, int K, int lda, int ldb, int ldc,
                             const float* __restrict__ bias, const float* __restrict__ gate,
                             const float* __restrict__ resid) {
    const int tid = threadIdx.x;
    const int m0 = blockIdx.y * 128, n0 = blockIdx.x * 128;
    const int tx = tid & 15, ty = tid >> 4;
    __shared__ float As[8][128];
    __shared__ float Bs[8][128];
    float acc[8][8];
#pragma unroll
    for (int i = 0; i < 8; i++)
#pragma unroll
        for (int j = 0; j < 8; j++) acc[i][j] = 0.f;

    for (int k0 = 0; k0 < K; k0 += 8) {
#pragma unroll
        for (int i = tid; i < 1024; i += 256) {
            int cc = i >> 7, r = i & 127;
            As[cc][r] = A[(size_t)(m0 + r) * lda + k0 + cc];
        }
#pragma unroll
        for (int i = tid; i < 1024; i += 256) {
            int r = i >> 7, cc = i & 127;
            Bs[r][cc] = B[(size_t)(k0 + r) * ldb + n0 + cc];
        }
        __syncthreads();
#pragma unroll
        for (int kk = 0; kk < 8; kk++) {
            float a[8], b[8];
            *(float4*)&a[0] = *(const float4*)&As[kk][ty * 8];
            *(float4*)&a[4] = *(const float4*)&As[kk][ty * 8 + 4];
            *(float4*)&b[0] = *(const float4*)&Bs[kk][tx * 8];
            *(float4*)&b[4] = *(const float4*)&Bs[kk][tx * 8 + 4];
#pragma unroll
            for (int i = 0; i < 8; i++)
#pragma unroll
                for (int j = 0; j < 8; j++) acc[i][j] += a[i] * b[j];
        }
        __syncthreads();
    }

#pragma unroll
    for (int i = 0; i < 8; i++) {
        int row = m0 + ty * 8 + i;
        float* cp = C + (size_t)row * ldc + n0 + tx * 8;
        float outv[8];
#pragma unroll
        for (int j = 0; j < 8; j++) {
            int col = n0 + tx * 8 + j;
            float v = acc[i][j];
            if (MODE == 1) {
                v = gelu_tanh(v + bias[col]);
            } else if (MODE == 2) {
                if (bias) v += bias[col];
                const float* rp = resid + (size_t)row * ldc + n0 + tx * 8;
                v = rp[j] + gate[col] * v;
            }
            outv[j] = v;
        }
        *(float4*)cp = *(float4*)&outv[0];
        *(float4*)(cp + 4) = *(float4*)&outv[4];
    }
}

// ---------------- RoPE applied in-place to q,k inside g_qkv ----------------
__global__ void rope_kernel(const float* __restrict__ cosb, const float* __restrict__ sinb) {
    int idx = blockIdx.x * blockDim.x + threadIdx.x;  // < T*HEADS*32
    int t = idx >> 9;
    int r = idx & 511;
    int h = r >> 5;
    int d = r & 31;
    float cc = cosb[t * 32 + d], ssn = sinb[t * 32 + d];
    size_t base = (size_t)t * 3072 + h * 64 + d;
    float q1 = g_qkv[base], q2 = g_qkv[base + 32];
    g_qkv[base] = q1 * cc - q2 * ssn;
    g_qkv[base + 32] = q2 * cc + q1 * ssn;
    size_t kb = base + 1024;
    float k1 = g_qkv[kb], k2 = g_qkv[kb + 32];
    g_qkv[kb] = k1 * cc - k2 * ssn;
    g_qkv[kb + 32] = k2 * cc + k1 * ssn;
}

// ---------------- fused flash attention (static smem, <48KB) ----------------
// One block per (32-row q tile, head). Online softmax; no score materialization.
// seq_idx sorted -> block-diagonal mask -> skip K tiles with no segment overlap.
// 256 threads: tx in [0,16) covers 64 kv cols (4 each), ty in [0,16) covers 32 q rows (2 each).
#define QROWS 32
#define QPAD 36
#define KPAD 68
__global__ void flash_kernel(const int* __restrict__ seq) {
    __shared__ float sQ[64 * QPAD];    // dim-major: sQ[k*QPAD + r], r < 32
    __shared__ float sKV[64 * KPAD];   // K: [k*KPAD + c]; V: [s*KPAD + c]
    __shared__ float sP[QROWS * KPAD]; // [r*KPAD + s]
    __shared__ int sq[QROWS];
    __shared__ int sk[64];

    const int head = blockIdx.y;
    const int m0 = blockIdx.x * QROWS;
    const int tid = threadIdx.x;
    const int tx = tid & 15, ty = tid >> 4;
    const float* Q = g_qkv + head * 64;
    const float* Kp = g_qkv + 1024 + head * 64;
    const float* V = g_qkv + 2048 + head * 64;

    // load Q tile (transposed to dim-major)
    for (int i = tid; i < QROWS * 64; i += 256) {
        int r = i >> 6, k = i & 63;
        sQ[k * QPAD + r] = Q[(size_t)(m0 + r) * 3072 + k];
    }
    if (tid < QROWS) sq[tid] = seq[m0 + tid];
    __syncthreads();

    const int sqmin = sq[0], sqmax = sq[QROWS - 1];
    int stq[2];
#pragma unroll
    for (int i = 0; i < 2; i++) stq[i] = sq[ty * 2 + i];

    float m_i[2], l_i[2], acc_o[2][4];
#pragma unroll
    for (int i = 0; i < 2; i++) {
        m_i[i] = -3e38f;
        l_i[i] = 0.f;
#pragma unroll
        for (int j = 0; j < 4; j++) acc_o[i][j] = 0.f;
    }

    for (int n0 = 0; n0 < TT; n0 += 64) {
        // segment-overlap tile skip (seq sorted)
        int kmin = seq[n0], kmax = seq[n0 + 63];
        if (kmax < sqmin || kmin > sqmax) continue;

        // load K tile (transposed) + seq_k
        for (int i = tid; i < 4096; i += 256) {
            int r = i >> 6, k = i & 63;
            sKV[k * KPAD + r] = Kp[(size_t)(n0 + r) * 3072 + k];
        }
        if (tid < 64) sk[tid] = seq[n0 + tid];
        __syncthreads();

        // S = Q @ K^T (2x4 per thread)
        float s_acc[2][4];
#pragma unroll
        for (int i = 0; i < 2; i++)
#pragma unroll
            for (int j = 0; j < 4; j++) s_acc[i][j] = 0.f;
#pragma unroll 8
        for (int kk = 0; kk < 64; kk++) {
            float a0 = sQ[kk * QPAD + ty * 2];
            float a1 = sQ[kk * QPAD + ty * 2 + 1];
            float b[4];
            *(float4*)b = *(const float4*)&sKV[kk * KPAD + tx * 4];
#pragma unroll
            for (int j = 0; j < 4; j++) {
                s_acc[0][j] += a0 * b[j];
                s_acc[1][j] += a1 * b[j];
            }
        }

        int stk[4];
#pragma unroll
        for (int j = 0; j < 4; j++) stk[j] = sk[tx * 4 + j];

        // mask + scale + online softmax update (per row; 16-lane reduce over tx)
#pragma unroll
        for (int i = 0; i < 2; i++) {
            float sv[4];
            float mt = -3e38f;
#pragma unroll
            for (int j = 0; j < 4; j++) {
                sv[j] = (stq[i] == stk[j]) ? s_acc[i][j] * 0.125f : -1e30f;
                mt = fmaxf(mt, sv[j]);
            }
#pragma unroll
            for (int o = 1; o < 16; o <<= 1) mt = fmaxf(mt, __shfl_xor_sync(0xffffffffu, mt, o));
            float mn = fmaxf(m_i[i], mt);
            float corr = __expf(m_i[i] - mn);
            float p[4];
            float ps = 0.f;
#pragma unroll
            for (int j = 0; j < 4; j++) {
                p[j] = __expf(sv[j] - mn);
                ps += p[j];
            }
#pragma unroll
            for (int o = 1; o < 16; o <<= 1) ps += __shfl_xor_sync(0xffffffffu, ps, o);
            l_i[i] = l_i[i] * corr + ps;
            m_i[i] = mn;
#pragma unroll
            for (int j = 0; j < 4; j++) acc_o[i][j] *= corr;
            *(float4*)&sP[(ty * 2 + i) * KPAD + tx * 4] = *(float4*)p;
        }
        __syncthreads();  // QK/sKV reads + sP writes done

        // load V tile (row-major) into sKV
        for (int i = tid; i < 4096; i += 256) {
            int r = i >> 6, c = i & 63;
            sKV[r * KPAD + c] = V[(size_t)(n0 + r) * 3072 + c];
        }
        __syncthreads();

        // O += P @ V
#pragma unroll 8
        for (int s = 0; s < 64; s++) {
            float b[4];
            *(float4*)b = *(const float4*)&sKV[s * KPAD + tx * 4];
            float a0 = sP[(ty * 2) * KPAD + s];
            float a1 = sP[(ty * 2 + 1) * KPAD + s];
#pragma unroll
            for (int j = 0; j < 4; j++) {
                acc_o[0][j] += a0 * b[j];
                acc_o[1][j] += a1 * b[j];
            }
        }
        __syncthreads();  // sKV/sP reads done before next tile
    }

    // write normalized output
#pragma unroll
    for (int i = 0; i < 2; i++) {
        float inv = 1.0f / l_i[i];
        float outv[4];
#pragma unroll
        for (int j = 0; j < 4; j++) outv[j] = acc_o[i][j] * inv;
        float* op = g_o + (size_t)(m0 + ty * 2 + i) * DIM + head * 64 + tx * 4;
        *(float4*)op = *(float4*)outv;
    }
}

// ---------------- launch ----------------
extern "C" void kernel_launch(void* const* d_in, const int* in_sizes, int n_in,
                              void* d_out, int out_size) {
    const float* x = (const float*)d_in[0];
    const float* c = (const float*)d_in[1];
    const float* cosb = (const float*)d_in[2];
    const float* sinb = (const float*)d_in[3];
    const int* seq = (const int*)d_in[4];
    const float* ln1_w = (const float*)d_in[5];
    const float* ln1_b = (const float*)d_in[6];
    const float* w_qkv = (const float*)d_in[7];
    const float* w_out = (const float*)d_in[8];
    const float* ln2_w = (const float*)d_in[9];
    const float* ln2_b = (const float*)d_in[10];
    const float* w_mlp1 = (const float*)d_in[11];
    const float* b_mlp1 = (const float*)d_in[12];
    const float* w_mlp2 = (const float*)d_in[13];
    const float* b_mlp2 = (const float*)d_in[14];
    const float* w_ada = (const float*)d_in[15];
    const float* b_ada = (const float*)d_in[16];
    float* out = (float*)d_out;

    float *ada, *h, *qkv, *o, *x1, *h2, *m;
    cudaGetSymbolAddress((void**)&ada, g_ada);
    cudaGetSymbolAddress((void**)&h, g_h);
    cudaGetSymbolAddress((void**)&qkv, g_qkv);
    cudaGetSymbolAddress((void**)&o, g_o);
    cudaGetSymbolAddress((void**)&x1, g_x1);
    cudaGetSymbolAddress((void**)&h2, g_h2);
    cudaGetSymbolAddress((void**)&m, g_m);

    // 1) adaLN vector
    ada_kernel<<<24, 256>>>(c, w_ada, b_ada);
    // 2) h = ln1(x)*(1+sc_msa)+sh_msa
    ln_mod_kernel<<<TT, 256>>>(x, ln1_w, ln1_b, ada + 1024, ada + 0, h);
    // 3) qkv = h @ w_qkv
    sgemm_kernel<0><<<dim3(3072 / 128, TT / 128), 256>>>(h, w_qkv, qkv, DIM, DIM, 3072, 3072,
                                                         nullptr, nullptr, nullptr);
    // 4) RoPE on q,k
    rope_kernel<<<(TT * HEADS * 32) / 256, 256>>>(cosb, sinb);
    // 5-7) fused masked attention (static smem)
    flash_kernel<<<dim3(TT / QROWS, HEADS), 256>>>(seq);
    // 8) x1 = x + g_msa * (O @ w_out)
    sgemm_kernel<2><<<dim3(DIM / 128, TT / 128), 256>>>(o, w_out, x1, DIM, DIM, DIM, DIM,
                                                        nullptr, ada + 2048, x);
    // 9) h2 = ln2(x1)*(1+sc_mlp)+sh_mlp
    ln_mod_kernel<<<TT, 256>>>(x1, ln2_w, ln2_b, ada + 4096, ada + 3072, h2);
    // 10) m = gelu(h2 @ w_mlp1 + b_mlp1)
    sgemm_kernel<1><<<dim3(MLPD / 128, TT / 128), 256>>>(h2, w_mlp1, m, DIM, DIM, MLPD, MLPD,
                                                         b_mlp1, nullptr, nullptr);
    // 11) out = x1 + g_mlp * (m @ w_mlp2 + b_mlp2)
    sgemm_kernel<2><<<dim3(DIM / 128, TT / 128), 256>>>(m, w_mlp2, out, MLPD, MLPD, DIM, DIM,
                                                        b_mlp2, ada + 5120, x1);
}

// round 4
// speedup vs baseline: 2.8423x; 2.8423x over previous
#include <cuda_runtime.h>
#include <math.h>
#include <stdint.h>

#define TT 4096
#define DIM 1024
#define HEADS 16
#define HD 64
#define MLPD 4096

// ---------------- scratch (device globals; no allocation allowed) ----------------
__device__ float g_ada[6 * DIM];
__device__ float g_h[TT * DIM];
__device__ float g_qkv[TT * 3 * DIM];
__device__ float g_o[TT * DIM];
__device__ float g_x1[TT * DIM];
__device__ float g_h2[TT * DIM];
__device__ float g_m[TT * MLPD];

// ---------------- helpers ----------------
__device__ __forceinline__ float gelu_tanh(float x) {
    float x3 = x * x * x;
    return 0.5f * x * (1.0f + tanhf(0.7978845608028654f * (x + 0.044715f * x3)));
}

__device__ __forceinline__ uint32_t f2tf32(float f) {
    uint32_t r;
    asm("cvt.rna.tf32.f32 %0, %1;" : "=r"(r) : "f"(f));
    return r;
}

// ---------------- ada = c @ w_ada + b_ada  (1x1024 @ 1024x6144) ----------------
__global__ void ada_kernel(const float* __restrict__ c, const float* __restrict__ w,
                           const float* __restrict__ b) {
    int j = blockIdx.x * blockDim.x + threadIdx.x;  // < 6144
    float s = b[j];
    for (int k = 0; k < DIM; k++) s += c[k] * w[k * 6144 + j];
    g_ada[j] = s;
}

// ---------------- LN + adaLN modulation: out = ln(x)*(1+sc)+sh ----------------
__global__ void ln_mod_kernel(const float* __restrict__ x, const float* __restrict__ w,
                              const float* __restrict__ bb, const float* __restrict__ sc,
                              const float* __restrict__ sh, float* __restrict__ out) {
    int t = blockIdx.x;
    int tid = threadIdx.x;
    int lane = tid & 31, wid = tid >> 5;
    __shared__ float red[8];
    float4 v = reinterpret_cast<const float4*>(x + (size_t)t * DIM)[tid];

    float s = v.x + v.y + v.z + v.w;
#pragma unroll
    for (int o = 16; o > 0; o >>= 1) s += __shfl_xor_sync(0xffffffffu, s, o);
    if (lane == 0) red[wid] = s;
    __syncthreads();
    float mu = 0.f;
#pragma unroll
    for (int i = 0; i < 8; i++) mu += red[i];
    mu *= (1.0f / DIM);

    float d0 = v.x - mu, d1 = v.y - mu, d2 = v.z - mu, d3 = v.w - mu;
    float ss = d0 * d0 + d1 * d1 + d2 * d2 + d3 * d3;
    __syncthreads();
#pragma unroll
    for (int o = 16; o > 0; o >>= 1) ss += __shfl_xor_sync(0xffffffffu, ss, o);
    if (lane == 0) red[wid] = ss;
    __syncthreads();
    float var = 0.f;
#pragma unroll
    for (int i = 0; i < 8; i++) var += red[i];
    var *= (1.0f / DIM);
    float rs = rsqrtf(var + 1e-5f);

    int j = tid * 4;
    float o0 = (d0 * rs * w[j + 0] + bb[j + 0]) * (1.0f + sc[j + 0]) + sh[j + 0];
    float o1 = (d1 * rs * w[j + 1] + bb[j + 1]) * (1.0f + sc[j + 1]) + sh[j + 1];
    float o2 = (d2 * rs * w[j + 2] + bb[j + 2]) * (1.0f + sc[j + 2]) + sh[j + 2];
    float o3 = (d3 * rs * w[j + 3] + bb[j + 3]) * (1.0f + sc[j + 3]) + sh[j + 3];
    reinterpret_cast<float4*>(out + (size_t)t * DIM)[tid] = make_float4(o0, o1, o2, o3);
}

// ---------------- TF32 tensor-core GEMM, 128x128x16 tiles -----------
// 256 threads = 8 warps in 4(M) x 2(N); warp tile 32x64; mma m16n8k8.
// MODE 0: C = A@B
// MODE 1: C = gelu(A@B + bias)
// MODE 2: C = resid + gate[col]*(A@B + bias?)
#define BM 128
#define BN 128
#define BK 16
template <int MODE>
__global__ void tgemm_kernel(const float* __restrict__ A, const float* __restrict__ B,
                             float* __restrict__ C, int K, int lda, int ldb, int ldc,
                             const float* __restrict__ bias, const float* __restrict__ gate,
                             const float* __restrict__ resid) {
    __shared__ uint32_t As[BM][BK + 4];   // m-major, pad 4
    __shared__ uint32_t Bs[BK][BN + 8];   // k-major, pad 8

    const int tid = threadIdx.x;
    const int lane = tid & 31;
    const int wid = tid >> 5;
    const int warp_m = wid & 3;   // 0..3
    const int warp_n = wid >> 2;  // 0..1
    const int m0 = blockIdx.y * BM, n0 = blockIdx.x * BN;
    const int lq = lane >> 2;     // 0..7
    const int lr = lane & 3;      // 0..3

    float acc[2][8][4];
#pragma unroll
    for (int i = 0; i < 2; i++)
#pragma unroll
        for (int j = 0; j < 8; j++)
#pragma unroll
            for (int r = 0; r < 4; r++) acc[i][j][r] = 0.f;

    const int arow = tid >> 1;            // 0..127
    const int akb = (tid & 1) * 8;        // 0 or 8

    for (int k0 = 0; k0 < K; k0 += BK) {
        // load A tile (128x16), convert to tf32, store m-major
        {
            const float* ap = A + (size_t)(m0 + arow) * lda + k0 + akb;
            float4 v0 = *(const float4*)ap;
            float4 v1 = *(const float4*)(ap + 4);
            As[arow][akb + 0] = f2tf32(v0.x);
            As[arow][akb + 1] = f2tf32(v0.y);
            As[arow][akb + 2] = f2tf32(v0.z);
            As[arow][akb + 3] = f2tf32(v0.w);
            As[arow][akb + 4] = f2tf32(v1.x);
            As[arow][akb + 5] = f2tf32(v1.y);
            As[arow][akb + 6] = f2tf32(v1.z);
            As[arow][akb + 7] = f2tf32(v1.w);
        }
        // load B tile (16x128), convert to tf32, store k-major
#pragma unroll
        for (int t = 0; t < 2; t++) {
            int i = tid + t * 256;
            int bk = i >> 5, bnq = i & 31;
            float4 v = *(const float4*)(B + (size_t)(k0 + bk) * ldb + n0 + bnq * 4);
            Bs[bk][bnq * 4 + 0] = f2tf32(v.x);
            Bs[bk][bnq * 4 + 1] = f2tf32(v.y);
            Bs[bk][bnq * 4 + 2] = f2tf32(v.z);
            Bs[bk][bnq * 4 + 3] = f2tf32(v.w);
        }
        __syncthreads();

#pragma unroll
        for (int ks = 0; ks < BK; ks += 8) {
            uint32_t a[2][4], b[8][2];
#pragma unroll
            for (int mt = 0; mt < 2; mt++) {
                int rb = warp_m * 32 + mt * 16 + lq;
                a[mt][0] = As[rb][ks + lr];
                a[mt][1] = As[rb + 8][ks + lr];
                a[mt][2] = As[rb][ks + 4 + lr];
                a[mt][3] = As[rb + 8][ks + 4 + lr];
            }
#pragma unroll
            for (int nt = 0; nt < 8; nt++) {
                int nb = warp_n * 64 + nt * 8 + lq;
                b[nt][0] = Bs[ks + lr][nb];
                b[nt][1] = Bs[ks + 4 + lr][nb];
            }
#pragma unroll
            for (int mt = 0; mt < 2; mt++)
#pragma unroll
                for (int nt = 0; nt < 8; nt++) {
                    asm volatile(
                        "mma.sync.aligned.m16n8k8.row.col.f32.tf32.tf32.f32 "
                        "{%0,%1,%2,%3}, {%4,%5,%6,%7}, {%8,%9}, {%0,%1,%2,%3};\n"
                        : "+f"(acc[mt][nt][0]), "+f"(acc[mt][nt][1]),
                          "+f"(acc[mt][nt][2]), "+f"(acc[mt][nt][3])
                        : "r"(a[mt][0]), "r"(a[mt][1]), "r"(a[mt][2]), "r"(a[mt][3]),
                          "r"(b[nt][0]), "r"(b[nt][1]));
                }
        }
        __syncthreads();
    }

    // epilogue: c0,c1 -> (row, col..col+1); c2,c3 -> (row+8, col..col+1)
#pragma unroll
    for (int mt = 0; mt < 2; mt++) {
#pragma unroll
        for (int nt = 0; nt < 8; nt++) {
            int row = m0 + warp_m * 32 + mt * 16 + lq;
            int col = n0 + warp_n * 64 + nt * 8 + lr * 2;
#pragma unroll
            for (int half = 0; half < 2; half++) {
                int r = row + half * 8;
                float v0 = acc[mt][nt][half * 2 + 0];
                float v1 = acc[mt][nt][half * 2 + 1];
                if (MODE == 1) {
                    v0 = gelu_tanh(v0 + bias[col]);
                    v1 = gelu_tanh(v1 + bias[col + 1]);
                } else if (MODE == 2) {
                    if (bias) { v0 += bias[col]; v1 += bias[col + 1]; }
                    const float* rp = resid + (size_t)r * ldc + col;
                    v0 = rp[0] + gate[col] * v0;
                    v1 = rp[1] + gate[col + 1] * v1;
                }
                *(float2*)(C + (size_t)r * ldc + col) = make_float2(v0, v1);
            }
        }
    }
}

// ---------------- RoPE applied in-place to q,k inside g_qkv ----------------
__global__ void rope_kernel(const float* __restrict__ cosb, const float* __restrict__ sinb) {
    int idx = blockIdx.x * blockDim.x + threadIdx.x;  // < T*HEADS*32
    int t = idx >> 9;
    int r = idx & 511;
    int h = r >> 5;
    int d = r & 31;
    float cc = cosb[t * 32 + d], ssn = sinb[t * 32 + d];
    size_t base = (size_t)t * 3072 + h * 64 + d;
    float q1 = g_qkv[base], q2 = g_qkv[base + 32];
    g_qkv[base] = q1 * cc - q2 * ssn;
    g_qkv[base + 32] = q2 * cc + q1 * ssn;
    size_t kb = base + 1024;
    float k1 = g_qkv[kb], k2 = g_qkv[kb + 32];
    g_qkv[kb] = k1 * cc - k2 * ssn;
    g_qkv[kb + 32] = k2 * cc + k1 * ssn;
}

// ---------------- fused flash attention (static smem, <48KB) ----------------
#define QROWS 32
#define QPAD 36
#define KPAD 68
__global__ void flash_kernel(const int* __restrict__ seq) {
    __shared__ float sQ[64 * QPAD];    // dim-major: sQ[k*QPAD + r], r < 32
    __shared__ float sKV[64 * KPAD];   // K: [k*KPAD + c]; V: [s*KPAD + c]
    __shared__ float sP[QROWS * KPAD]; // [r*KPAD + s]
    __shared__ int sq[QROWS];
    __shared__ int sk[64];

    const int head = blockIdx.y;
    const int m0 = blockIdx.x * QROWS;
    const int tid = threadIdx.x;
    const int tx = tid & 15, ty = tid >> 4;
    const float* Q = g_qkv + head * 64;
    const float* Kp = g_qkv + 1024 + head * 64;
    const float* V = g_qkv + 2048 + head * 64;

    for (int i = tid; i < QROWS * 64; i += 256) {
        int r = i >> 6, k = i & 63;
        sQ[k * QPAD + r] = Q[(size_t)(m0 + r) * 3072 + k];
    }
    if (tid < QROWS) sq[tid] = seq[m0 + tid];
    __syncthreads();

    const int sqmin = sq[0], sqmax = sq[QROWS - 1];
    int stq[2];
#pragma unroll
    for (int i = 0; i < 2; i++) stq[i] = sq[ty * 2 + i];

    float m_i[2], l_i[2], acc_o[2][4];
#pragma unroll
    for (int i = 0; i < 2; i++) {
        m_i[i] = -3e38f;
        l_i[i] = 0.f;
#pragma unroll
        for (int j = 0; j < 4; j++) acc_o[i][j] = 0.f;
    }

    for (int n0 = 0; n0 < TT; n0 += 64) {
        int kmin = seq[n0], kmax = seq[n0 + 63];
        if (kmax < sqmin || kmin > sqmax) continue;

        for (int i = tid; i < 4096; i += 256) {
            int r = i >> 6, k = i & 63;
            sKV[k * KPAD + r] = Kp[(size_t)(n0 + r) * 3072 + k];
        }
        if (tid < 64) sk[tid] = seq[n0 + tid];
        __syncthreads();

        float s_acc[2][4];
#pragma unroll
        for (int i = 0; i < 2; i++)
#pragma unroll
            for (int j = 0; j < 4; j++) s_acc[i][j] = 0.f;
#pragma unroll 8
        for (int kk = 0; kk < 64; kk++) {
            float a0 = sQ[kk * QPAD + ty * 2];
            float a1 = sQ[kk * QPAD + ty * 2 + 1];
            float b[4];
            *(float4*)b = *(const float4*)&sKV[kk * KPAD + tx * 4];
#pragma unroll
            for (int j = 0; j < 4; j++) {
                s_acc[0][j] += a0 * b[j];
                s_acc[1][j] += a1 * b[j];
            }
        }

        int stk[4];
#pragma unroll
        for (int j = 0; j < 4; j++) stk[j] = sk[tx * 4 + j];

#pragma unroll
        for (int i = 0; i < 2; i++) {
            float sv[4];
            float mt = -3e38f;
#pragma unroll
            for (int j = 0; j < 4; j++) {
                sv[j] = (stq[i] == stk[j]) ? s_acc[i][j] * 0.125f : -1e30f;
                mt = fmaxf(mt, sv[j]);
            }
#pragma unroll
            for (int o = 1; o < 16; o <<= 1) mt = fmaxf(mt, __shfl_xor_sync(0xffffffffu, mt, o));
            float mn = fmaxf(m_i[i], mt);
            float corr = __expf(m_i[i] - mn);
            float p[4];
            float ps = 0.f;
#pragma unroll
            for (int j = 0; j < 4; j++) {
                p[j] = __expf(sv[j] - mn);
                ps += p[j];
            }
#pragma unroll
            for (int o = 1; o < 16; o <<= 1) ps += __shfl_xor_sync(0xffffffffu, ps, o);
            l_i[i] = l_i[i] * corr + ps;
            m_i[i] = mn;
#pragma unroll
            for (int j = 0; j < 4; j++) acc_o[i][j] *= corr;
            *(float4*)&sP[(ty * 2 + i) * KPAD + tx * 4] = *(float4*)p;
        }
        __syncthreads();

        for (int i = tid; i < 4096; i += 256) {
            int r = i >> 6, c = i & 63;
            sKV[r * KPAD + c] = V[(size_t)(n0 + r) * 3072 + c];
        }
        __syncthreads();

#pragma unroll 8
        for (int s = 0; s < 64; s++) {
            float b[4];
            *(float4*)b = *(const float4*)&sKV[s * KPAD + tx * 4];
            float a0 = sP[(ty * 2) * KPAD + s];
            float a1 = sP[(ty * 2 + 1) * KPAD + s];
#pragma unroll
            for (int j = 0; j < 4; j++) {
                acc_o[0][j] += a0 * b[j];
                acc_o[1][j] += a1 * b[j];
            }
        }
        __syncthreads();
    }

#pragma unroll
    for (int i = 0; i < 2; i++) {
        float inv = 1.0f / l_i[i];
        float outv[4];
#pragma unroll
        for (int j = 0; j < 4; j++) outv[j] = acc_o[i][j] * inv;
        float* op = g_o + (size_t)(m0 + ty * 2 + i) * DIM + head * 64 + tx * 4;
        *(float4*)op = *(float4*)outv;
    }
}

// ---------------- launch ----------------
extern "C" void kernel_launch(void* const* d_in, const int* in_sizes, int n_in,
                              void* d_out, int out_size) {
    const float* x = (const float*)d_in[0];
    const float* c = (const float*)d_in[1];
    const float* cosb = (const float*)d_in[2];
    const float* sinb = (const float*)d_in[3];
    const int* seq = (const int*)d_in[4];
    const float* ln1_w = (const float*)d_in[5];
    const float* ln1_b = (const float*)d_in[6];
    const float* w_qkv = (const float*)d_in[7];
    const float* w_out = (const float*)d_in[8];
    const float* ln2_w = (const float*)d_in[9];
    const float* ln2_b = (const float*)d_in[10];
    const float* w_mlp1 = (const float*)d_in[11];
    const float* b_mlp1 = (const float*)d_in[12];
    const float* w_mlp2 = (const float*)d_in[13];
    const float* b_mlp2 = (const float*)d_in[14];
    const float* w_ada = (const float*)d_in[15];
    const float* b_ada = (const float*)d_in[16];
    float* out = (float*)d_out;

    float *ada, *h, *qkv, *o, *x1, *h2, *m;
    cudaGetSymbolAddress((void**)&ada, g_ada);
    cudaGetSymbolAddress((void**)&h, g_h);
    cudaGetSymbolAddress((void**)&qkv, g_qkv);
    cudaGetSymbolAddress((void**)&o, g_o);
    cudaGetSymbolAddress((void**)&x1, g_x1);
    cudaGetSymbolAddress((void**)&h2, g_h2);
    cudaGetSymbolAddress((void**)&m, g_m);

    // 1) adaLN vector
    ada_kernel<<<24, 256>>>(c, w_ada, b_ada);
    // 2) h = ln1(x)*(1+sc_msa)+sh_msa
    ln_mod_kernel<<<TT, 256>>>(x, ln1_w, ln1_b, ada + 1024, ada + 0, h);
    // 3) qkv = h @ w_qkv
    tgemm_kernel<0><<<dim3(3072 / BN, TT / BM), 256>>>(h, w_qkv, qkv, DIM, DIM, 3072, 3072,
                                                       nullptr, nullptr, nullptr);
    // 4) RoPE on q,k
    rope_kernel<<<(TT * HEADS * 32) / 256, 256>>>(cosb, sinb);
    // 5-7) fused masked attention (static smem)
    flash_kernel<<<dim3(TT / QROWS, HEADS), 256>>>(seq);
    // 8) x1 = x + g_msa * (O @ w_out)
    tgemm_kernel<2><<<dim3(DIM / BN, TT / BM), 256>>>(o, w_out, x1, DIM, DIM, DIM, DIM,
                                                      nullptr, ada + 2048, x);
    // 9) h2 = ln2(x1)*(1+sc_mlp)+sh_mlp
    ln_mod_kernel<<<TT, 256>>>(x1, ln2_w, ln2_b, ada + 4096, ada + 3072, h2);
    // 10) m = gelu(h2 @ w_mlp1 + b_mlp1)
    tgemm_kernel<1><<<dim3(MLPD / BN, TT / BM), 256>>>(h2, w_mlp1, m, DIM, DIM, MLPD, MLPD,
                                                       b_mlp1, nullptr, nullptr);
    // 11) out = x1 + g_mlp * (m @ w_mlp2 + b_mlp2)
    tgemm_kernel<2><<<dim3(DIM / BN, TT / BM), 256>>>(m, w_mlp2, out, MLPD, MLPD, DIM, DIM,
                                                      b_mlp2, ada + 5120, x1);
}

// round 5
// speedup vs baseline: 3.9319x; 1.3833x over previous
#include <cuda_runtime.h>
#include <math.h>
#include <stdint.h>

#define TT 4096
#define DIM 1024
#define HEADS 16
#define HD 64
#define MLPD 4096

// ---------------- scratch (device globals; no allocation allowed) ----------------
__device__ float g_ada[6 * DIM];
__device__ float g_h[TT * DIM];
__device__ float g_qkv[TT * 3 * DIM];
__device__ float g_o[TT * DIM];
__device__ float g_x1[TT * DIM];
__device__ float g_h2[TT * DIM];
__device__ float g_m[TT * MLPD];

// ---------------- helpers ----------------
__device__ __forceinline__ float gelu_tanh(float x) {
    float x3 = x * x * x;
    return 0.5f * x * (1.0f + tanhf(0.7978845608028654f * (x + 0.044715f * x3)));
}

__device__ __forceinline__ uint32_t f2tf32(float f) {
    uint32_t r;
    asm("cvt.rna.tf32.f32 %0, %1;" : "=r"(r) : "f"(f));
    return r;
}

__device__ __forceinline__ void mma_tf32(float* c, const uint32_t* a, uint32_t b0, uint32_t b1) {
    asm volatile(
        "mma.sync.aligned.m16n8k8.row.col.f32.tf32.tf32.f32 "
        "{%0,%1,%2,%3}, {%4,%5,%6,%7}, {%8,%9}, {%0,%1,%2,%3};\n"
        : "+f"(c[0]), "+f"(c[1]), "+f"(c[2]), "+f"(c[3])
        : "r"(a[0]), "r"(a[1]), "r"(a[2]), "r"(a[3]), "r"(b0), "r"(b1));
}

// ---------------- ada = c @ w_ada + b_ada  (1x1024 @ 1024x6144) ----------------
__global__ void ada_kernel(const float* __restrict__ c, const float* __restrict__ w,
                           const float* __restrict__ b) {
    int j = blockIdx.x * blockDim.x + threadIdx.x;  // < 6144
    float s = b[j];
    for (int k = 0; k < DIM; k++) s += c[k] * w[k * 6144 + j];
    g_ada[j] = s;
}

// ---------------- LN + adaLN modulation: out = ln(x)*(1+sc)+sh ----------------
__global__ void ln_mod_kernel(const float* __restrict__ x, const float* __restrict__ w,
                              const float* __restrict__ bb, const float* __restrict__ sc,
                              const float* __restrict__ sh, float* __restrict__ out) {
    int t = blockIdx.x;
    int tid = threadIdx.x;
    int lane = tid & 31, wid = tid >> 5;
    __shared__ float red[8];
    float4 v = reinterpret_cast<const float4*>(x + (size_t)t * DIM)[tid];

    float s = v.x + v.y + v.z + v.w;
#pragma unroll
    for (int o = 16; o > 0; o >>= 1) s += __shfl_xor_sync(0xffffffffu, s, o);
    if (lane == 0) red[wid] = s;
    __syncthreads();
    float mu = 0.f;
#pragma unroll
    for (int i = 0; i < 8; i++) mu += red[i];
    mu *= (1.0f / DIM);

    float d0 = v.x - mu, d1 = v.y - mu, d2 = v.z - mu, d3 = v.w - mu;
    float ss = d0 * d0 + d1 * d1 + d2 * d2 + d3 * d3;
    __syncthreads();
#pragma unroll
    for (int o = 16; o > 0; o >>= 1) ss += __shfl_xor_sync(0xffffffffu, ss, o);
    if (lane == 0) red[wid] = ss;
    __syncthreads();
    float var = 0.f;
#pragma unroll
    for (int i = 0; i < 8; i++) var += red[i];
    var *= (1.0f / DIM);
    float rs = rsqrtf(var + 1e-5f);

    int j = tid * 4;
    float o0 = (d0 * rs * w[j + 0] + bb[j + 0]) * (1.0f + sc[j + 0]) + sh[j + 0];
    float o1 = (d1 * rs * w[j + 1] + bb[j + 1]) * (1.0f + sc[j + 1]) + sh[j + 1];
    float o2 = (d2 * rs * w[j + 2] + bb[j + 2]) * (1.0f + sc[j + 2]) + sh[j + 2];
    float o3 = (d3 * rs * w[j + 3] + bb[j + 3]) * (1.0f + sc[j + 3]) + sh[j + 3];
    reinterpret_cast<float4*>(out + (size_t)t * DIM)[tid] = make_float4(o0, o1, o2, o3);
}

// ---------------- TF32 tensor-core GEMM, 128x128x16 tiles, double-buffered -----------
// 256 threads = 8 warps in 4(M) x 2(N); warp tile 32x64; mma m16n8k8.
// MODE 0: C = A@B ; MODE 1: C = gelu(A@B + bias) ; MODE 2: C = resid + gate[col]*(A@B + bias?)
#define BM 128
#define BN 128
#define BK 16
template <int MODE>
__global__ void tgemm_kernel(const float* __restrict__ A, const float* __restrict__ B,
                             float* __restrict__ C, int K, int lda, int ldb, int ldc,
                             const float* __restrict__ bias, const float* __restrict__ gate,
                             const float* __restrict__ resid) {
    __shared__ uint32_t As[2][BM][BK + 4];   // m-major, pad 4
    __shared__ uint32_t Bs[2][BK][BN + 8];   // k-major, pad 8

    const int tid = threadIdx.x;
    const int lane = tid & 31;
    const int wid = tid >> 5;
    const int warp_m = wid & 3;
    const int warp_n = wid >> 2;
    const int m0 = blockIdx.y * BM, n0 = blockIdx.x * BN;
    const int lq = lane >> 2;
    const int lr = lane & 3;

    float acc[2][8][4];
#pragma unroll
    for (int i = 0; i < 2; i++)
#pragma unroll
        for (int j = 0; j < 8; j++)
#pragma unroll
            for (int r = 0; r < 4; r++) acc[i][j][r] = 0.f;

    const int arow = tid >> 1;
    const int akb = (tid & 1) * 8;
    const int bk0 = tid >> 5, bn4a = tid & 31;  // t=0 chunk
    // t=1 chunk: bk0+8, same bn4a

    // initial tile 0 -> stage 0
    {
        const float* ap = A + (size_t)(m0 + arow) * lda + akb;
        float4 v0 = *(const float4*)ap;
        float4 v1 = *(const float4*)(ap + 4);
        As[0][arow][akb + 0] = f2tf32(v0.x); As[0][arow][akb + 1] = f2tf32(v0.y);
        As[0][arow][akb + 2] = f2tf32(v0.z); As[0][arow][akb + 3] = f2tf32(v0.w);
        As[0][arow][akb + 4] = f2tf32(v1.x); As[0][arow][akb + 5] = f2tf32(v1.y);
        As[0][arow][akb + 6] = f2tf32(v1.z); As[0][arow][akb + 7] = f2tf32(v1.w);
        float4 w0 = *(const float4*)(B + (size_t)bk0 * ldb + n0 + bn4a * 4);
        float4 w1 = *(const float4*)(B + (size_t)(bk0 + 8) * ldb + n0 + bn4a * 4);
        Bs[0][bk0][bn4a * 4 + 0] = f2tf32(w0.x); Bs[0][bk0][bn4a * 4 + 1] = f2tf32(w0.y);
        Bs[0][bk0][bn4a * 4 + 2] = f2tf32(w0.z); Bs[0][bk0][bn4a * 4 + 3] = f2tf32(w0.w);
        Bs[0][bk0 + 8][bn4a * 4 + 0] = f2tf32(w1.x); Bs[0][bk0 + 8][bn4a * 4 + 1] = f2tf32(w1.y);
        Bs[0][bk0 + 8][bn4a * 4 + 2] = f2tf32(w1.z); Bs[0][bk0 + 8][bn4a * 4 + 3] = f2tf32(w1.w);
    }
    __syncthreads();

    int cur = 0;
    for (int k0 = 0; k0 < K; k0 += BK) {
        float4 pa0, pa1, pb0, pb1;
        const bool more = (k0 + BK < K);
        if (more) {
            const float* ap = A + (size_t)(m0 + arow) * lda + k0 + BK + akb;
            pa0 = *(const float4*)ap;
            pa1 = *(const float4*)(ap + 4);
            pb0 = *(const float4*)(B + (size_t)(k0 + BK + bk0) * ldb + n0 + bn4a * 4);
            pb1 = *(const float4*)(B + (size_t)(k0 + BK + bk0 + 8) * ldb + n0 + bn4a * 4);
        }

#pragma unroll
        for (int ks = 0; ks < BK; ks += 8) {
            uint32_t a[2][4], b[8][2];
#pragma unroll
            for (int mt = 0; mt < 2; mt++) {
                int rb = warp_m * 32 + mt * 16 + lq;
                a[mt][0] = As[cur][rb][ks + lr];
                a[mt][1] = As[cur][rb + 8][ks + lr];
                a[mt][2] = As[cur][rb][ks + 4 + lr];
                a[mt][3] = As[cur][rb + 8][ks + 4 + lr];
            }
#pragma unroll
            for (int nt = 0; nt < 8; nt++) {
                int nb = warp_n * 64 + nt * 8 + lq;
                b[nt][0] = Bs[cur][ks + lr][nb];
                b[nt][1] = Bs[cur][ks + 4 + lr][nb];
            }
#pragma unroll
            for (int mt = 0; mt < 2; mt++)
#pragma unroll
                for (int nt = 0; nt < 8; nt++)
                    mma_tf32(acc[mt][nt], a[mt], b[nt][0], b[nt][1]);
        }

        if (more) {
            int nx = cur ^ 1;
            As[nx][arow][akb + 0] = f2tf32(pa0.x); As[nx][arow][akb + 1] = f2tf32(pa0.y);
            As[nx][arow][akb + 2] = f2tf32(pa0.z); As[nx][arow][akb + 3] = f2tf32(pa0.w);
            As[nx][arow][akb + 4] = f2tf32(pa1.x); As[nx][arow][akb + 5] = f2tf32(pa1.y);
            As[nx][arow][akb + 6] = f2tf32(pa1.z); As[nx][arow][akb + 7] = f2tf32(pa1.w);
            Bs[nx][bk0][bn4a * 4 + 0] = f2tf32(pb0.x); Bs[nx][bk0][bn4a * 4 + 1] = f2tf32(pb0.y);
            Bs[nx][bk0][bn4a * 4 + 2] = f2tf32(pb0.z); Bs[nx][bk0][bn4a * 4 + 3] = f2tf32(pb0.w);
            Bs[nx][bk0 + 8][bn4a * 4 + 0] = f2tf32(pb1.x); Bs[nx][bk0 + 8][bn4a * 4 + 1] = f2tf32(pb1.y);
            Bs[nx][bk0 + 8][bn4a * 4 + 2] = f2tf32(pb1.z); Bs[nx][bk0 + 8][bn4a * 4 + 3] = f2tf32(pb1.w);
        }
        __syncthreads();
        cur ^= 1;
    }

    // epilogue
#pragma unroll
    for (int mt = 0; mt < 2; mt++) {
#pragma unroll
        for (int nt = 0; nt < 8; nt++) {
            int row = m0 + warp_m * 32 + mt * 16 + lq;
            int col = n0 + warp_n * 64 + nt * 8 + lr * 2;
#pragma unroll
            for (int half = 0; half < 2; half++) {
                int r = row + half * 8;
                float v0 = acc[mt][nt][half * 2 + 0];
                float v1 = acc[mt][nt][half * 2 + 1];
                if (MODE == 1) {
                    v0 = gelu_tanh(v0 + bias[col]);
                    v1 = gelu_tanh(v1 + bias[col + 1]);
                } else if (MODE == 2) {
                    if (bias) { v0 += bias[col]; v1 += bias[col + 1]; }
                    const float* rp = resid + (size_t)r * ldc + col;
                    v0 = rp[0] + gate[col] * v0;
                    v1 = rp[1] + gate[col + 1] * v1;
                }
                *(float2*)(C + (size_t)r * ldc + col) = make_float2(v0, v1);
            }
        }
    }
}

// ---------------- RoPE applied in-place to q,k inside g_qkv ----------------
__global__ void rope_kernel(const float* __restrict__ cosb, const float* __restrict__ sinb) {
    int idx = blockIdx.x * blockDim.x + threadIdx.x;  // < T*HEADS*32
    int t = idx >> 9;
    int r = idx & 511;
    int h = r >> 5;
    int d = r & 31;
    float cc = cosb[t * 32 + d], ssn = sinb[t * 32 + d];
    size_t base = (size_t)t * 3072 + h * 64 + d;
    float q1 = g_qkv[base], q2 = g_qkv[base + 32];
    g_qkv[base] = q1 * cc - q2 * ssn;
    g_qkv[base + 32] = q2 * cc + q1 * ssn;
    size_t kb = base + 1024;
    float k1 = g_qkv[kb], k2 = g_qkv[kb + 32];
    g_qkv[kb] = k1 * cc - k2 * ssn;
    g_qkv[kb + 32] = k2 * cc + k1 * ssn;
}

// ---------------- tensor-core flash attention ----------------
// 64 q-rows per block, 128 threads (4 warps); warp w owns rows w*16..w*16+15.
// tf32 m16n8k8 for QK and PV; online softmax in accumulator fragment layout.
#define FQ 64
#define FST 68
__global__ void flash2_kernel(const int* __restrict__ seq) {
    __shared__ uint32_t sKV[64 * FST];  // tf32 bits; K then V, row=kv idx, col=dim
    __shared__ uint32_t sP[64 * FST];   // Q staging, then P (tf32)
    __shared__ int sk[64];

    const int head = blockIdx.y;
    const int m0 = blockIdx.x * FQ;
    const int tid = threadIdx.x;
    const int lane = tid & 31;
    const int wm = tid >> 5;  // 0..3
    const int lq = lane >> 2, lr = lane & 3;

    const float* Q = g_qkv + head * 64;
    const float* Kp = g_qkv + 1024 + head * 64;
    const float* V = g_qkv + 2048 + head * 64;

    // stage Q -> sP (tf32), then pull fragments to registers
    for (int i = tid; i < 4096; i += 128) {
        int r = i >> 6, d = i & 63;
        sP[r * FST + d] = f2tf32(Q[(size_t)(m0 + r) * 3072 + d]);
    }
    __syncthreads();
    uint32_t qf[8][4];
    {
        const int rb = wm * 16 + lq;
#pragma unroll
        for (int ks = 0; ks < 8; ks++) {
            qf[ks][0] = sP[rb * FST + ks * 8 + lr];
            qf[ks][1] = sP[(rb + 8) * FST + ks * 8 + lr];
            qf[ks][2] = sP[rb * FST + ks * 8 + 4 + lr];
            qf[ks][3] = sP[(rb + 8) * FST + ks * 8 + 4 + lr];
        }
    }
    __syncthreads();

    const int stq0 = seq[m0 + wm * 16 + lq];
    const int stq1 = seq[m0 + wm * 16 + lq + 8];
    const int sqmin = seq[m0], sqmax = seq[m0 + FQ - 1];

    float mi[2] = {-3e38f, -3e38f}, li[2] = {0.f, 0.f};
    float oacc[8][4];
#pragma unroll
    for (int nt = 0; nt < 8; nt++)
#pragma unroll
        for (int r = 0; r < 4; r++) oacc[nt][r] = 0.f;

    for (int n0 = 0; n0 < TT; n0 += 64) {
        int kmin = seq[n0], kmax = seq[n0 + 63];
        if (kmax < sqmin || kmin > sqmax) continue;

        // K tile -> sKV (tf32)
        for (int i = tid; i < 4096; i += 128) {
            int r = i >> 6, d = i & 63;
            sKV[r * FST + d] = f2tf32(Kp[(size_t)(n0 + r) * 3072 + d]);
        }
        if (tid < 64) sk[tid] = seq[n0 + tid];
        __syncthreads();

        // S = Q @ K^T
        float sacc[8][4];
#pragma unroll
        for (int nt = 0; nt < 8; nt++)
#pragma unroll
            for (int r = 0; r < 4; r++) sacc[nt][r] = 0.f;
#pragma unroll
        for (int nt = 0; nt < 8; nt++) {
#pragma unroll
            for (int ks = 0; ks < 8; ks++) {
                uint32_t b0 = sKV[(nt * 8 + lq) * FST + ks * 8 + lr];
                uint32_t b1 = sKV[(nt * 8 + lq) * FST + ks * 8 + 4 + lr];
                mma_tf32(sacc[nt], qf[ks], b0, b1);
            }
        }

        // mask + scale
        int skc0[8], skc1[8];
#pragma unroll
        for (int nt = 0; nt < 8; nt++) {
            skc0[nt] = sk[nt * 8 + 2 * lr];
            skc1[nt] = sk[nt * 8 + 2 * lr + 1];
        }
        float mt[2] = {-3e38f, -3e38f};
#pragma unroll
        for (int nt = 0; nt < 8; nt++) {
            sacc[nt][0] = (stq0 == skc0[nt]) ? sacc[nt][0] * 0.125f : -1e30f;
            sacc[nt][1] = (stq0 == skc1[nt]) ? sacc[nt][1] * 0.125f : -1e30f;
            sacc[nt][2] = (stq1 == skc0[nt]) ? sacc[nt][2] * 0.125f : -1e30f;
            sacc[nt][3] = (stq1 == skc1[nt]) ? sacc[nt][3] * 0.125f : -1e30f;
            mt[0] = fmaxf(mt[0], fmaxf(sacc[nt][0], sacc[nt][1]));
            mt[1] = fmaxf(mt[1], fmaxf(sacc[nt][2], sacc[nt][3]));
        }
#pragma unroll
        for (int h = 0; h < 2; h++) {
            mt[h] = fmaxf(mt[h], __shfl_xor_sync(0xffffffffu, mt[h], 1));
            mt[h] = fmaxf(mt[h], __shfl_xor_sync(0xffffffffu, mt[h], 2));
        }
        float corr[2], mn[2];
#pragma unroll
        for (int h = 0; h < 2; h++) {
            mn[h] = fmaxf(mi[h], mt[h]);
            corr[h] = __expf(mi[h] - mn[h]);
            mi[h] = mn[h];
        }
        float ps[2] = {0.f, 0.f};
        const int prow = wm * 16 + lq;
#pragma unroll
        for (int nt = 0; nt < 8; nt++) {
            float p0 = __expf(sacc[nt][0] - mn[0]);
            float p1 = __expf(sacc[nt][1] - mn[0]);
            float p2 = __expf(sacc[nt][2] - mn[1]);
            float p3 = __expf(sacc[nt][3] - mn[1]);
            ps[0] += p0 + p1;
            ps[1] += p2 + p3;
            sP[prow * FST + nt * 8 + 2 * lr] = f2tf32(p0);
            sP[prow * FST + nt * 8 + 2 * lr + 1] = f2tf32(p1);
            sP[(prow + 8) * FST + nt * 8 + 2 * lr] = f2tf32(p2);
            sP[(prow + 8) * FST + nt * 8 + 2 * lr + 1] = f2tf32(p3);
        }
#pragma unroll
        for (int h = 0; h < 2; h++) {
            ps[h] += __shfl_xor_sync(0xffffffffu, ps[h], 1);
            ps[h] += __shfl_xor_sync(0xffffffffu, ps[h], 2);
            li[h] = li[h] * corr[h] + ps[h];
        }
#pragma unroll
        for (int nt = 0; nt < 8; nt++) {
            oacc[nt][0] *= corr[0];
            oacc[nt][1] *= corr[0];
            oacc[nt][2] *= corr[1];
            oacc[nt][3] *= corr[1];
        }
        __syncthreads();  // QK reads done; P visible

        // V tile -> sKV (tf32)
        for (int i = tid; i < 4096; i += 128) {
            int r = i >> 6, d = i & 63;
            sKV[r * FST + d] = f2tf32(V[(size_t)(n0 + r) * 3072 + d]);
        }
        __syncthreads();

        // O += P @ V
#pragma unroll
        for (int ks = 0; ks < 8; ks++) {
            uint32_t a[4];
            a[0] = sP[prow * FST + ks * 8 + lr];
            a[1] = sP[(prow + 8) * FST + ks * 8 + lr];
            a[2] = sP[prow * FST + ks * 8 + 4 + lr];
            a[3] = sP[(prow + 8) * FST + ks * 8 + 4 + lr];
#pragma unroll
            for (int nt = 0; nt < 8; nt++) {
                uint32_t b0 = sKV[(ks * 8 + lr) * FST + nt * 8 + lq];
                uint32_t b1 = sKV[(ks * 8 + 4 + lr) * FST + nt * 8 + lq];
                mma_tf32(oacc[nt], a, b0, b1);
            }
        }
        __syncthreads();  // sKV/sP reads done before next tile
    }

    // normalized output
    const float inv0 = 1.0f / li[0];
    const float inv1 = 1.0f / li[1];
    const int row0 = m0 + wm * 16 + lq;
#pragma unroll
    for (int nt = 0; nt < 8; nt++) {
        int col = head * 64 + nt * 8 + 2 * lr;
        *(float2*)(g_o + (size_t)row0 * DIM + col) =
            make_float2(oacc[nt][0] * inv0, oacc[nt][1] * inv0);
        *(float2*)(g_o + (size_t)(row0 + 8) * DIM + col) =
            make_float2(oacc[nt][2] * inv1, oacc[nt][3] * inv1);
    }
}

// ---------------- launch ----------------
extern "C" void kernel_launch(void* const* d_in, const int* in_sizes, int n_in,
                              void* d_out, int out_size) {
    const float* x = (const float*)d_in[0];
    const float* c = (const float*)d_in[1];
    const float* cosb = (const float*)d_in[2];
    const float* sinb = (const float*)d_in[3];
    const int* seq = (const int*)d_in[4];
    const float* ln1_w = (const float*)d_in[5];
    const float* ln1_b = (const float*)d_in[6];
    const float* w_qkv = (const float*)d_in[7];
    const float* w_out = (const float*)d_in[8];
    const float* ln2_w = (const float*)d_in[9];
    const float* ln2_b = (const float*)d_in[10];
    const float* w_mlp1 = (const float*)d_in[11];
    const float* b_mlp1 = (const float*)d_in[12];
    const float* w_mlp2 = (const float*)d_in[13];
    const float* b_mlp2 = (const float*)d_in[14];
    const float* w_ada = (const float*)d_in[15];
    const float* b_ada = (const float*)d_in[16];
    float* out = (float*)d_out;

    float *ada, *h, *qkv, *o, *x1, *h2, *m;
    cudaGetSymbolAddress((void**)&ada, g_ada);
    cudaGetSymbolAddress((void**)&h, g_h);
    cudaGetSymbolAddress((void**)&qkv, g_qkv);
    cudaGetSymbolAddress((void**)&o, g_o);
    cudaGetSymbolAddress((void**)&x1, g_x1);
    cudaGetSymbolAddress((void**)&h2, g_h2);
    cudaGetSymbolAddress((void**)&m, g_m);

    // 1) adaLN vector
    ada_kernel<<<24, 256>>>(c, w_ada, b_ada);
    // 2) h = ln1(x)*(1+sc_msa)+sh_msa
    ln_mod_kernel<<<TT, 256>>>(x, ln1_w, ln1_b, ada + 1024, ada + 0, h);
    // 3) qkv = h @ w_qkv
    tgemm_kernel<0><<<dim3(3072 / BN, TT / BM), 256>>>(h, w_qkv, qkv, DIM, DIM, 3072, 3072,
                                                       nullptr, nullptr, nullptr);
    // 4) RoPE on q,k
    rope_kernel<<<(TT * HEADS * 32) / 256, 256>>>(cosb, sinb);
    // 5-7) fused masked attention (tensor cores)
    flash2_kernel<<<dim3(TT / FQ, HEADS), 128>>>(seq);
    // 8) x1 = x + g_msa * (O @ w_out)
    tgemm_kernel<2><<<dim3(DIM / BN, TT / BM), 256>>>(o, w_out, x1, DIM, DIM, DIM, DIM,
                                                      nullptr, ada + 2048, x);
    // 9) h2 = ln2(x1)*(1+sc_mlp)+sh_mlp
    ln_mod_kernel<<<TT, 256>>>(x1, ln2_w, ln2_b, ada + 4096, ada + 3072, h2);
    // 10) m = gelu(h2 @ w_mlp1 + b_mlp1)
    tgemm_kernel<1><<<dim3(MLPD / BN, TT / BM), 256>>>(h2, w_mlp1, m, DIM, DIM, MLPD, MLPD,
                                                       b_mlp1, nullptr, nullptr);
    // 11) out = x1 + g_mlp * (m @ w_mlp2 + b_mlp2)
    tgemm_kernel<2><<<dim3(DIM / BN, TT / BM), 256>>>(m, w_mlp2, out, MLPD, MLPD, DIM, DIM,
                                                      b_mlp2, ada + 5120, x1);
}